// round 11
// baseline (speedup 1.0000x reference)
#include <cuda_runtime.h>
#include <math.h>

#define NN 4096
#define DD 256
#define CAPR 128      // row candidate capacity (fast path)
#define CCAP 1024     // per-column candidate capacity (global)

// ---------------- device scratch ----------------
__device__ unsigned g_colmax_enc[NN];                 // encoded col max of -cost
__device__ float    g_colthr[NN];                     // colmax - 1
__device__ int      g_colcnt[NN];
__device__ float    g_colval[(size_t)NN * CCAP];
__device__ unsigned short g_colrow[(size_t)NN * CCAP];
__device__ float g_tau_col[NN];
__device__ float g_beta[(size_t)NN * DD];
__device__ float g_alpha[(size_t)NN * DD];
__device__ float g_v1[DD];
__device__ float g_v2[DD];
__device__ float g_y;

// monotonic float<->unsigned encoding for atomicMax
__device__ __forceinline__ unsigned encf(float f) {
    unsigned i = __float_as_uint(f);
    return (i & 0x80000000u) ? ~i : (i | 0x80000000u);
}
__device__ __forceinline__ float decf(unsigned u) {
    return (u & 0x80000000u) ? __uint_as_float(u & 0x7fffffffu) : __uint_as_float(~u);
}

// ---------------- warp helpers ----------------
__device__ __forceinline__ float warpRedSum(float v) {
#pragma unroll
    for (int o = 16; o > 0; o >>= 1) v += __shfl_xor_sync(0xffffffffu, v, o);
    return v;
}
__device__ __forceinline__ float warpRedMax(float v) {
#pragma unroll
    for (int o = 16; o > 0; o >>= 1) v = fmaxf(v, __shfl_xor_sync(0xffffffffu, v, o));
    return v;
}

__device__ __forceinline__ int blockScanExcl(int cnt, int& total, int tid) {
    __shared__ int warp_tot[8];
    const unsigned mask = 0xffffffffu;
    int lane = tid & 31, w = tid >> 5;
    int incl = cnt;
#pragma unroll
    for (int o = 1; o < 32; o <<= 1) {
        int n = __shfl_up_sync(mask, incl, o);
        if (lane >= o) incl += n;
    }
    if (lane == 31) warp_tot[w] = incl;
    __syncthreads();
    if (w == 0) {
        int t = (lane < 8) ? warp_tot[lane] : 0;
#pragma unroll
        for (int o = 1; o < 8; o <<= 1) {
            int n = __shfl_up_sync(mask, t, o);
            if (lane >= o) t += n;
        }
        if (lane < 8) warp_tot[lane] = t;
    }
    __syncthreads();
    int warp_off = (w == 0) ? 0 : warp_tot[w - 1];
    total = warp_tot[7];
    __syncthreads();
    return warp_off + incl - cnt;
}

// ---------------- kernels ----------------
__global__ void zero_kernel() {
    int t = blockIdx.x * 256 + threadIdx.x;   // grid 16 -> 4096 threads
    g_colcnt[t] = 0;
    g_colmax_enc[t] = 0u;
    if (t < DD) { g_v1[t] = 0.f; g_v2[t] = 0.f; }
}

// per-column max of -cost: 64-row x 256-col tiles
__global__ __launch_bounds__(256) void colmax_kernel(const float* __restrict__ cost) {
    int c = blockIdx.x * 256 + threadIdx.x;
    size_t r0 = (size_t)blockIdx.y * 64;
    float m = -3.0e38f;
#pragma unroll 8
    for (int r = 0; r < 64; r++)
        m = fmaxf(m, -cost[(r0 + r) * NN + c]);
    atomicMax(&g_colmax_enc[c], encf(m));
}

__global__ void thr_kernel() {
    int t = blockIdx.x * 256 + threadIdx.x;
    g_colthr[t] = decf(g_colmax_enc[t]) - 1.0f;
}

// row sparsemax: one early candidate compaction, warp-redundant barrier-free
// Michelot, a0 write, column-candidate harvest, branchless batched beta mix.
__global__ __launch_bounds__(256) void spmax_row_kernel(const float* __restrict__ cost,
                                                        float* __restrict__ a0,
                                                        const float* __restrict__ colvecs) {
    __shared__ float red[8 + 64];    // [0..7] max partials; rest for fallback parity bufs
    __shared__ float s_v[CAPR];
    __shared__ unsigned short s_jj[CAPR];
    int tid = threadIdx.x;   // 256
    int lane = tid & 31;
    int row = blockIdx.x;
    const float* xrow = cost + (size_t)row * NN;

    float x[16];
    float vmax = -3.0e38f;
#pragma unroll
    for (int k = 0; k < 4; k++) {
        float4 v = *(const float4*)(xrow + tid * 4 + k * 1024);
        x[k * 4 + 0] = -v.x; x[k * 4 + 1] = -v.y;
        x[k * 4 + 2] = -v.z; x[k * 4 + 3] = -v.w;
        vmax = fmaxf(vmax, fmaxf(fmaxf(-v.x, -v.y), fmaxf(-v.z, -v.w)));
    }

    // block max
    float m = warpRedMax(vmax);
    if (lane == 0) red[tid >> 5] = m;
    __syncthreads();
    float bm = red[0];
#pragma unroll
    for (int i = 1; i < 8; i++) bm = fmaxf(bm, red[i]);
    const float thr_row = bm - 1.0f;   // tau* >= thr_row -> candidates suffice

    // one-shot candidate compaction {x > thr_row} (~26 expected)
    int cnt = 0;
#pragma unroll
    for (int s = 0; s < 16; s++)
        if (x[s] > thr_row) cnt++;
    int nnz;
    int base = blockScanExcl(cnt, nnz, tid);
    bool fast = (nnz <= CAPR);
    if (fast) {
        int pos = base;
#pragma unroll
        for (int s = 0; s < 16; s++) {
            if (x[s] > thr_row) {
                s_v[pos] = x[s];
                s_jj[pos] = (unsigned short)(tid * 4 + (s >> 2) * 1024 + (s & 3));
                pos++;
            }
        }
    }
    __syncthreads();

    float tau;
    if (fast) {
        // every warp redundantly: Michelot on the list, shuffle-only (no barriers)
        float v0 = (lane      < nnz) ? s_v[lane]      : -3.0e38f;
        float v1 = (lane + 32 < nnz) ? s_v[lane + 32] : -3.0e38f;
        float v2 = (lane + 64 < nnz) ? s_v[lane + 64] : -3.0e38f;
        float v3 = (lane + 96 < nnz) ? s_v[lane + 96] : -3.0e38f;
        float ls = warpRedSum(((lane < nnz) ? v0 : 0.f) + ((lane + 32 < nnz) ? v1 : 0.f) +
                              ((lane + 64 < nnz) ? v2 : 0.f) + ((lane + 96 < nnz) ? v3 : 0.f));
        float t = (ls - 1.0f) / (float)nnz;
        int kprev = nnz;
        for (int it = 0; it < 48; ++it) {
            float s = 0.f, c = 0.f;
            if (v0 > t) { s += v0; c += 1.0f; }
            if (v1 > t) { s += v1; c += 1.0f; }
            if (v2 > t) { s += v2; c += 1.0f; }
            if (v3 > t) { s += v3; c += 1.0f; }
            s = warpRedSum(s);
            c = warpRedSum(c);
            int k = (int)c;
            if (k == kprev) break;
            t = (s - 1.0f) / c;
            kprev = k;
        }
        tau = t;   // identical across all warps
    } else {
        // fallback: block-wide register Michelot (old proven path)
        tau = thr_row;
        int kprev = -1;
        for (int it = 0; it < 64; ++it) {
            float ls = 0.f, lc = 0.f;
#pragma unroll
            for (int s = 0; s < 16; s++) {
                float v = x[s];
                if (v > tau) { ls += v; lc += 1.0f; }
            }
            ls = warpRedSum(ls);
            lc = warpRedSum(lc);
            int p = it & 1;
            float* buf = red + 8 + p * 32;
            if (lane == 0) { buf[tid >> 5] = ls; buf[8 + (tid >> 5)] = lc; }
            __syncthreads();
            float S = 0.f, K = 0.f;
#pragma unroll
            for (int i = 0; i < 8; i++) { S += buf[i]; K += buf[8 + i]; }
            int k = (int)K;
            if (k == kprev) break;
            tau = (S - 1.0f) / K;
            kprev = k;
        }
    }

    // a0 + column candidate harvest (x > colmax[j]-1)
#pragma unroll
    for (int k = 0; k < 4; k++) {
        int j = tid * 4 + k * 1024;
        float4 o;
        o.x = fmaxf(x[k * 4 + 0] - tau, 0.f);
        o.y = fmaxf(x[k * 4 + 1] - tau, 0.f);
        o.z = fmaxf(x[k * 4 + 2] - tau, 0.f);
        o.w = fmaxf(x[k * 4 + 3] - tau, 0.f);
        __stcs((float4*)(a0 + (size_t)row * NN + j), o);

        float4 th = *(const float4*)(g_colthr + j);
#pragma unroll
        for (int c = 0; c < 4; c++) {
            float xv = x[k * 4 + c];
            float tt = (c == 0) ? th.x : (c == 1) ? th.y : (c == 2) ? th.z : th.w;
            if (xv > tt) {
                int jj = j + c;
                int pos = atomicAdd(&g_colcnt[jj], 1);
                if (pos < CCAP) {
                    g_colval[(size_t)jj * CCAP + pos] = xv;
                    g_colrow[(size_t)jj * CCAP + pos] = (unsigned short)row;
                }
            }
        }
    }

    // beta mix straight off the candidate list (branchless weights, MLP-4 loads)
    float acc0 = 0.f, acc1 = 0.f;
    if (fast) {
        int n = 0;
        for (; n + 4 <= nnz; n += 4) {
            float p0 = fmaxf(s_v[n + 0] - tau, 0.f);
            float p1 = fmaxf(s_v[n + 1] - tau, 0.f);
            float p2 = fmaxf(s_v[n + 2] - tau, 0.f);
            float p3 = fmaxf(s_v[n + 3] - tau, 0.f);
            float m0 = colvecs[(size_t)s_jj[n + 0] * DD + tid];
            float m1 = colvecs[(size_t)s_jj[n + 1] * DD + tid];
            float m2 = colvecs[(size_t)s_jj[n + 2] * DD + tid];
            float m3 = colvecs[(size_t)s_jj[n + 3] * DD + tid];
            acc0 = fmaf(p0, m0, acc0);
            acc1 = fmaf(p1, m1, acc1);
            acc0 = fmaf(p2, m2, acc0);
            acc1 = fmaf(p3, m3, acc1);
        }
        for (; n < nnz; n++)
            acc0 = fmaf(fmaxf(s_v[n] - tau, 0.f), colvecs[(size_t)s_jj[n] * DD + tid], acc0);
    } else {
        for (int j = 0; j < NN; j++) {
            float p = -xrow[j] - tau;
            if (p > 0.f) acc0 = fmaf(p, colvecs[(size_t)j * DD + tid], acc0);
        }
    }
    g_beta[(size_t)row * DD + tid] = acc0 + acc1;
}

// per-column: exact Michelot on candidate list -> tau_col + alpha[j,:]
__global__ __launch_bounds__(256) void col_alpha_kernel(const float* __restrict__ cost,
                                                        const float* __restrict__ rowvecs) {
    __shared__ float sv[CCAP];
    __shared__ unsigned short si[CCAP];
    __shared__ float s_tau;
    int j = blockIdx.x;
    int tid = threadIdx.x, lane = tid & 31;
    int cnt = g_colcnt[j];

    if (cnt <= CCAP) {
        for (int n = tid; n < cnt; n += 256) {
            sv[n] = g_colval[(size_t)j * CCAP + n];
            si[n] = g_colrow[(size_t)j * CCAP + n];
        }
        __syncthreads();
        if (tid < 32) {
            float ls = 0.f;
            for (int n = lane; n < cnt; n += 32) ls += sv[n];
            ls = warpRedSum(ls);
            float t = (ls - 1.0f) / (float)cnt;
            int kprev = cnt;
            for (int it = 0; it < 48; ++it) {
                float s = 0.f, c = 0.f;
                for (int n = lane; n < cnt; n += 32) {
                    float v = sv[n];
                    if (v > t) { s += v; c += 1.0f; }
                }
                s = warpRedSum(s);
                c = warpRedSum(c);
                int k = (int)c;
                if (k == kprev) break;
                t = (s - 1.0f) / c;
                kprev = k;
            }
            if (lane == 0) s_tau = t;
        }
        __syncthreads();
        float tau = s_tau;
        if (tid == 0) g_tau_col[j] = tau;

        for (int n = tid; n < cnt; n += 256)
            sv[n] = fmaxf(sv[n] - tau, 0.f);
        __syncthreads();

        float acc0 = 0.f, acc1 = 0.f;
        int n = 0;
        for (; n + 4 <= cnt; n += 4) {
            float p0 = sv[n + 0], p1 = sv[n + 1], p2 = sv[n + 2], p3 = sv[n + 3];
            float m0 = rowvecs[(size_t)si[n + 0] * DD + tid];
            float m1 = rowvecs[(size_t)si[n + 1] * DD + tid];
            float m2 = rowvecs[(size_t)si[n + 2] * DD + tid];
            float m3 = rowvecs[(size_t)si[n + 3] * DD + tid];
            acc0 = fmaf(p0, m0, acc0);
            acc1 = fmaf(p1, m1, acc1);
            acc0 = fmaf(p2, m2, acc0);
            acc1 = fmaf(p3, m3, acc1);
        }
        for (; n < cnt; n++)
            acc0 = fmaf(sv[n], rowvecs[(size_t)si[n] * DD + tid], acc0);
        g_alpha[(size_t)j * DD + tid] = acc0 + acc1;
    } else {
        if (tid < 32) {
            float t = g_colthr[j];
            int kprev = -1;
            for (int it = 0; it < 64; ++it) {
                float s = 0.f, c = 0.f;
                for (int r = lane; r < NN; r += 32) {
                    float v = -cost[(size_t)r * NN + j];
                    if (v > t) { s += v; c += 1.0f; }
                }
                s = warpRedSum(s);
                c = warpRedSum(c);
                int k = (int)c;
                if (k == kprev) break;
                t = (s - 1.0f) / c;
                kprev = k;
            }
            if (lane == 0) s_tau = t;
        }
        __syncthreads();
        float tau = s_tau;
        if (tid == 0) g_tau_col[j] = tau;
        float acc = 0.f;
        for (int r = 0; r < NN; r++) {
            float p = -cost[(size_t)r * NN + j] - tau;
            if (p > 0.f) acc = fmaf(p, rowvecs[(size_t)r * DD + tid], acc);
        }
        g_alpha[(size_t)j * DD + tid] = acc;
    }
}

// leaky_relu(X @ W + b) partial means — packed f32x2 FMA; grid (256, 2)
__global__ __launch_bounds__(256) void g_mean_kernel(const float* __restrict__ Wg,
                                                     const float* __restrict__ bg) {
    int which = blockIdx.y;
    const float* Xall = which ? g_alpha : g_beta;
    float* gv = which ? g_v2 : g_v1;
    __shared__ unsigned long long xs2[8 * 256];
    int tid = threadIdx.x;
    size_t r0 = (size_t)blockIdx.x * 16;

#pragma unroll
    for (int i = 0; i < 8; i++) {
        float a = Xall[(r0 + 2 * i) * 256 + tid];
        float b = Xall[(r0 + 2 * i + 1) * 256 + tid];
        unsigned long long p;
        asm("mov.b64 %0, {%1, %2};" : "=l"(p) : "f"(a), "f"(b));
        xs2[i * 256 + tid] = p;
    }
    __syncthreads();

    unsigned long long acc[8];
#pragma unroll
    for (int i = 0; i < 8; i++) acc[i] = 0ull;

    for (int k0 = 0; k0 < 256; k0 += 8) {
        float w[8];
#pragma unroll
        for (int u = 0; u < 8; u++) w[u] = Wg[(size_t)(k0 + u) * 256 + tid];
#pragma unroll
        for (int u = 0; u < 8; u += 2) {
            unsigned long long wd0, wd1;
            asm("mov.b64 %0, {%1, %1};" : "=l"(wd0) : "f"(w[u]));
            asm("mov.b64 %0, {%1, %1};" : "=l"(wd1) : "f"(w[u + 1]));
#pragma unroll
            for (int i = 0; i < 8; i++) {
                ulonglong2 xv = *(const ulonglong2*)&xs2[i * 256 + k0 + u];
                asm("fma.rn.f32x2 %0, %1, %2, %0;" : "+l"(acc[i]) : "l"(xv.x), "l"(wd0));
                asm("fma.rn.f32x2 %0, %1, %2, %0;" : "+l"(acc[i]) : "l"(xv.y), "l"(wd1));
            }
        }
    }

    float bb = bg[tid], s = 0.f;
#pragma unroll
    for (int i = 0; i < 8; i++) {
        float lo, hi;
        asm("mov.b64 {%0, %1}, %2;" : "=f"(lo), "=f"(hi) : "l"(acc[i]));
        float z0 = lo + bb, z1 = hi + bb;
        s += (z0 > 0.f) ? z0 : 0.2f * z0;
        s += (z1 > 0.f) ? z1 : 0.2f * z1;
    }
    atomicAdd(&gv[tid], s);
}

__global__ void cosine_kernel() {
    __shared__ float red[24];
    int tid = threadIdx.x;
    float v1 = g_v1[tid] * (1.0f / NN);
    float v2 = g_v2[tid] * (1.0f / NN);
    float d = v1 * v2, a = v1 * v1, b = v2 * v2;
    d = warpRedSum(d); a = warpRedSum(a); b = warpRedSum(b);
    if ((tid & 31) == 0) {
        red[tid >> 5] = d; red[8 + (tid >> 5)] = a; red[16 + (tid >> 5)] = b;
    }
    __syncthreads();
    if (tid == 0) {
        float D = 0.f, A = 0.f, B = 0.f;
#pragma unroll
        for (int i = 0; i < 8; i++) { D += red[i]; A += red[8 + i]; B += red[16 + i]; }
        g_y = 1.0f - D / (sqrtf(A) * sqrtf(B) + 1e-8f);
    }
}

// fused tail: a1[i,j] = max(-cost[i,j] - tau_col[j], 0)  AND  cost_out = y
__global__ void tail_kernel(const float* __restrict__ cost,
                            float* __restrict__ a1, float* __restrict__ cost_out) {
    size_t idx = ((size_t)blockIdx.x * blockDim.x + threadIdx.x) * 4;
    int j = (int)(idx & (NN - 1));
    float4 c = *(const float4*)(cost + idx);
    const float4 tc = *(const float4*)(g_tau_col + j);
    float4 o;
    o.x = fmaxf(-c.x - tc.x, 0.f);
    o.y = fmaxf(-c.y - tc.y, 0.f);
    o.z = fmaxf(-c.z - tc.z, 0.f);
    o.w = fmaxf(-c.w - tc.w, 0.f);
    __stcs((float4*)(a1 + idx), o);
    float y = g_y;
    __stcs((float4*)(cost_out + idx), make_float4(y, y, y, y));
}

// ---------------- launch ----------------
extern "C" void kernel_launch(void* const* d_in, const int* in_sizes, int n_in,
                              void* d_out, int out_size) {
    const float* row_vecs    = (const float*)d_in[0];
    const float* column_vecs = (const float*)d_in[1];
    const float* cost        = (const float*)d_in[2];
    const float* W_G         = (const float*)d_in[3];
    const float* b_G         = (const float*)d_in[4];

    float* out      = (float*)d_out;
    float* cost_out = out;
    float* a0       = out + (size_t)NN * NN;
    float* a1       = out + 2 * (size_t)NN * NN;

    (void)in_sizes; (void)n_in; (void)out_size;

    zero_kernel<<<16, 256>>>();
    colmax_kernel<<<dim3(NN / 256, NN / 64), 256>>>(cost);
    thr_kernel<<<16, 256>>>();
    spmax_row_kernel<<<NN, 256>>>(cost, a0, column_vecs);   // a0, beta, col candidates
    col_alpha_kernel<<<NN, 256>>>(cost, row_vecs);          // tau_col, alpha
    g_mean_kernel<<<dim3(NN / 16, 2), 256>>>(W_G, b_G);     // v1 & v2
    cosine_kernel<<<1, 256>>>();
    tail_kernel<<<(NN * (size_t)NN) / (4 * 256), 256>>>(cost, a1, cost_out);
}

// round 12
// speedup vs baseline: 1.6452x; 1.6452x over previous
#include <cuda_runtime.h>
#include <math.h>

#define NN 4096
#define DD 256
#define CAPS 1024     // row support capacity (smem)
#define CCAP 1024     // per-column candidate capacity (global)

// ---------------- device scratch ----------------
__device__ unsigned g_colmax_enc[NN];                 // encoded col max of -cost
__device__ float    g_colthr[NN];                     // colmax - 1
__device__ int      g_colcnt[NN];
__device__ float    g_colval[(size_t)NN * CCAP];
__device__ unsigned short g_colrow[(size_t)NN * CCAP];
__device__ float g_tau_col[NN];
__device__ float g_beta[(size_t)NN * DD];
__device__ float g_alpha[(size_t)NN * DD];
__device__ float g_v1[DD];
__device__ float g_v2[DD];
__device__ float g_y;

// monotonic float<->unsigned encoding for atomicMax
__device__ __forceinline__ unsigned encf(float f) {
    unsigned i = __float_as_uint(f);
    return (i & 0x80000000u) ? ~i : (i | 0x80000000u);
}
__device__ __forceinline__ float decf(unsigned u) {
    return (u & 0x80000000u) ? __uint_as_float(u & 0x7fffffffu) : __uint_as_float(~u);
}

// ---------------- warp helpers ----------------
__device__ __forceinline__ float warpRedSum(float v) {
#pragma unroll
    for (int o = 16; o > 0; o >>= 1) v += __shfl_xor_sync(0xffffffffu, v, o);
    return v;
}
__device__ __forceinline__ float warpRedMax(float v) {
#pragma unroll
    for (int o = 16; o > 0; o >>= 1) v = fmaxf(v, __shfl_xor_sync(0xffffffffu, v, o));
    return v;
}

__device__ __forceinline__ int blockScanExcl(int cnt, int& total, int tid) {
    __shared__ int warp_tot[8];
    const unsigned mask = 0xffffffffu;
    int lane = tid & 31, w = tid >> 5;
    int incl = cnt;
#pragma unroll
    for (int o = 1; o < 32; o <<= 1) {
        int n = __shfl_up_sync(mask, incl, o);
        if (lane >= o) incl += n;
    }
    if (lane == 31) warp_tot[w] = incl;
    __syncthreads();
    if (w == 0) {
        int t = (lane < 8) ? warp_tot[lane] : 0;
#pragma unroll
        for (int o = 1; o < 8; o <<= 1) {
            int n = __shfl_up_sync(mask, t, o);
            if (lane >= o) t += n;
        }
        if (lane < 8) warp_tot[lane] = t;
    }
    __syncthreads();
    int warp_off = (w == 0) ? 0 : warp_tot[w - 1];
    total = warp_tot[7];
    __syncthreads();
    return warp_off + incl - cnt;
}

// ---------------- kernels ----------------
__global__ void zero_kernel() {
    int t = blockIdx.x * 256 + threadIdx.x;   // grid 16 -> 4096 threads
    g_colcnt[t] = 0;
    g_colmax_enc[t] = 0u;
    if (t < DD) { g_v1[t] = 0.f; g_v2[t] = 0.f; }
}

// per-column max of -cost: 64-row x 256-col tiles
__global__ __launch_bounds__(256) void colmax_kernel(const float* __restrict__ cost) {
    int c = blockIdx.x * 256 + threadIdx.x;
    size_t r0 = (size_t)blockIdx.y * 64;
    float m = -3.0e38f;
#pragma unroll 8
    for (int r = 0; r < 64; r++)
        m = fmaxf(m, -cost[(r0 + r) * NN + c]);
    atomicMax(&g_colmax_enc[c], encf(m));
}

__global__ void thr_kernel() {
    int t = blockIdx.x * 256 + threadIdx.x;
    g_colthr[t] = decf(g_colmax_enc[t]) - 1.0f;
}

// row sparsemax + a0 + beta mix + column-candidate harvest
__global__ __launch_bounds__(256) void spmax_row_kernel(const float* __restrict__ cost,
                                                        float* __restrict__ a0,
                                                        const float* __restrict__ colvecs) {
    __shared__ float red[8 + 64];
    __shared__ float s_p[CAPS];
    __shared__ unsigned short s_j[CAPS];
    int tid = threadIdx.x;   // 256
    int row = blockIdx.x;
    const float* xrow = cost + (size_t)row * NN;

    float x[16];
    float vmax = -3.0e38f;
#pragma unroll
    for (int k = 0; k < 4; k++) {
        float4 v = *(const float4*)(xrow + tid * 4 + k * 1024);
        x[k * 4 + 0] = -v.x; x[k * 4 + 1] = -v.y;
        x[k * 4 + 2] = -v.z; x[k * 4 + 3] = -v.w;
        vmax = fmaxf(vmax, fmaxf(fmaxf(-v.x, -v.y), fmaxf(-v.z, -v.w)));
    }

    float m = warpRedMax(vmax);
    if ((tid & 31) == 0) red[tid >> 5] = m;
    __syncthreads();
    float bm = red[0];
#pragma unroll
    for (int i = 1; i < 8; i++) bm = fmaxf(bm, red[i]);

    float tau = bm - 1.0f;   // tau0 <= tau*: Michelot-valid start
    int kprev = -1;
    for (int it = 0; it < 64; ++it) {
        float ls = 0.f, lc = 0.f;
#pragma unroll
        for (int s = 0; s < 16; s++) {
            float v = x[s];
            if (v > tau) { ls += v; lc += 1.0f; }
        }
        ls = warpRedSum(ls);
        lc = warpRedSum(lc);
        int p = it & 1;
        float* buf = red + 8 + p * 32;
        if ((tid & 31) == 0) { buf[tid >> 5] = ls; buf[8 + (tid >> 5)] = lc; }
        __syncthreads();
        float S = 0.f, K = 0.f;
#pragma unroll
        for (int i = 0; i < 8; i++) { S += buf[i]; K += buf[8 + i]; }
        int k = (int)K;
        if (k == kprev) break;
        tau = (S - 1.0f) / K;
        kprev = k;
    }

    // a0 + column candidate harvest (x > colmax[j]-1)
#pragma unroll
    for (int k = 0; k < 4; k++) {
        int j = tid * 4 + k * 1024;
        float4 o;
        o.x = fmaxf(x[k * 4 + 0] - tau, 0.f);
        o.y = fmaxf(x[k * 4 + 1] - tau, 0.f);
        o.z = fmaxf(x[k * 4 + 2] - tau, 0.f);
        o.w = fmaxf(x[k * 4 + 3] - tau, 0.f);
        __stcs((float4*)(a0 + (size_t)row * NN + j), o);

        float4 th = *(const float4*)(g_colthr + j);
#pragma unroll
        for (int c = 0; c < 4; c++) {
            float xv = x[k * 4 + c];
            float tt = (c == 0) ? th.x : (c == 1) ? th.y : (c == 2) ? th.z : th.w;
            if (xv > tt) {
                int jj = j + c;
                int pos = atomicAdd(&g_colcnt[jj], 1);
                if (pos < CCAP) {
                    g_colval[(size_t)jj * CCAP + pos] = xv;
                    g_colrow[(size_t)jj * CCAP + pos] = (unsigned short)row;
                }
            }
        }
    }

    // row support compaction + beta mix
    int cnt = 0;
#pragma unroll
    for (int s = 0; s < 16; s++)
        if (x[s] > tau) cnt++;
    int nnz;
    int base = blockScanExcl(cnt, nnz, tid);
    if (nnz <= CAPS) {
        int pos = base;
#pragma unroll
        for (int s = 0; s < 16; s++) {
            if (x[s] > tau) {
                s_p[pos] = x[s] - tau;
                s_j[pos] = (unsigned short)(tid * 4 + (s >> 2) * 1024 + (s & 3));
                pos++;
            }
        }
    }
    __syncthreads();

    float acc = 0.f;
    if (nnz <= CAPS) {
#pragma unroll 4
        for (int n = 0; n < nnz; n++)
            acc = fmaf(s_p[n], colvecs[(size_t)s_j[n] * DD + tid], acc);
    } else {
        for (int j = 0; j < NN; j++) {
            float p = -xrow[j] - tau;
            if (p > 0.f) acc = fmaf(p, colvecs[(size_t)j * DD + tid], acc);
        }
    }
    g_beta[(size_t)row * DD + tid] = acc;
}

// per-column: exact Michelot on candidate list -> tau_col + alpha[j,:]
// branchless weight precompute + 4-batched unconditional loads (MLP 4)
__global__ __launch_bounds__(256) void col_alpha_kernel(const float* __restrict__ cost,
                                                        const float* __restrict__ rowvecs) {
    __shared__ float sv[CCAP];
    __shared__ unsigned short si[CCAP];
    __shared__ float s_tau;
    int j = blockIdx.x;
    int tid = threadIdx.x, lane = tid & 31;
    int cnt = g_colcnt[j];

    if (cnt <= CCAP) {
        for (int n = tid; n < cnt; n += 256) {
            sv[n] = g_colval[(size_t)j * CCAP + n];
            si[n] = g_colrow[(size_t)j * CCAP + n];
        }
        __syncthreads();
        if (tid < 32) {
            float ls = 0.f;
            for (int n = lane; n < cnt; n += 32) ls += sv[n];
            ls = warpRedSum(ls);
            float t = (ls - 1.0f) / (float)cnt;   // Michelot start: full list
            int kprev = cnt;
            for (int it = 0; it < 48; ++it) {
                float s = 0.f, c = 0.f;
                for (int n = lane; n < cnt; n += 32) {
                    float v = sv[n];
                    if (v > t) { s += v; c += 1.0f; }
                }
                s = warpRedSum(s);
                c = warpRedSum(c);
                int k = (int)c;
                if (k == kprev) break;
                t = (s - 1.0f) / c;
                kprev = k;
            }
            if (lane == 0) s_tau = t;
        }
        __syncthreads();
        float tau = s_tau;
        if (tid == 0) g_tau_col[j] = tau;

        // branchless in-place weights: sv[n] = max(sv[n] - tau, 0)
        for (int n = tid; n < cnt; n += 256)
            sv[n] = fmaxf(sv[n] - tau, 0.f);
        __syncthreads();

        // mix with unconditional 4-batched loads, dual accumulators
        float acc0 = 0.f, acc1 = 0.f;
        int n = 0;
        for (; n + 4 <= cnt; n += 4) {
            float p0 = sv[n + 0], p1 = sv[n + 1], p2 = sv[n + 2], p3 = sv[n + 3];
            float m0 = rowvecs[(size_t)si[n + 0] * DD + tid];
            float m1 = rowvecs[(size_t)si[n + 1] * DD + tid];
            float m2 = rowvecs[(size_t)si[n + 2] * DD + tid];
            float m3 = rowvecs[(size_t)si[n + 3] * DD + tid];
            acc0 = fmaf(p0, m0, acc0);
            acc1 = fmaf(p1, m1, acc1);
            acc0 = fmaf(p2, m2, acc0);
            acc1 = fmaf(p3, m3, acc1);
        }
        for (; n < cnt; n++)
            acc0 = fmaf(sv[n], rowvecs[(size_t)si[n] * DD + tid], acc0);
        g_alpha[(size_t)j * DD + tid] = acc0 + acc1;
    } else {
        // dense fallback (never expected): warp Michelot over the raw column
        if (tid < 32) {
            float t = g_colthr[j];
            int kprev = -1;
            for (int it = 0; it < 64; ++it) {
                float s = 0.f, c = 0.f;
                for (int r = lane; r < NN; r += 32) {
                    float v = -cost[(size_t)r * NN + j];
                    if (v > t) { s += v; c += 1.0f; }
                }
                s = warpRedSum(s);
                c = warpRedSum(c);
                int k = (int)c;
                if (k == kprev) break;
                t = (s - 1.0f) / c;
                kprev = k;
            }
            if (lane == 0) s_tau = t;
        }
        __syncthreads();
        float tau = s_tau;
        if (tid == 0) g_tau_col[j] = tau;
        float acc = 0.f;
        for (int r = 0; r < NN; r++) {
            float p = -cost[(size_t)r * NN + j] - tau;
            if (p > 0.f) acc = fmaf(p, rowvecs[(size_t)r * DD + tid], acc);
        }
        g_alpha[(size_t)j * DD + tid] = acc;
    }
}

// leaky_relu(X @ W + b) partial means — packed f32x2 FMA; grid (512, 2)
// 8 rows per block (4 packed pairs) -> 1024 blocks for latency hiding
__global__ __launch_bounds__(256) void g_mean_kernel(const float* __restrict__ Wg,
                                                     const float* __restrict__ bg) {
    int which = blockIdx.y;
    const float* Xall = which ? g_alpha : g_beta;
    float* gv = which ? g_v2 : g_v1;
    __shared__ unsigned long long xs2[4 * 256];
    int tid = threadIdx.x;
    size_t r0 = (size_t)blockIdx.x * 8;

#pragma unroll
    for (int i = 0; i < 4; i++) {
        float a = Xall[(r0 + 2 * i) * 256 + tid];
        float b = Xall[(r0 + 2 * i + 1) * 256 + tid];
        unsigned long long p;
        asm("mov.b64 %0, {%1, %2};" : "=l"(p) : "f"(a), "f"(b));
        xs2[i * 256 + tid] = p;
    }
    __syncthreads();

    unsigned long long acc[4];
#pragma unroll
    for (int i = 0; i < 4; i++) acc[i] = 0ull;

    for (int k0 = 0; k0 < 256; k0 += 8) {
        float w[8];
#pragma unroll
        for (int u = 0; u < 8; u++) w[u] = Wg[(size_t)(k0 + u) * 256 + tid];
#pragma unroll
        for (int u = 0; u < 8; u += 2) {
            unsigned long long wd0, wd1;
            asm("mov.b64 %0, {%1, %1};" : "=l"(wd0) : "f"(w[u]));
            asm("mov.b64 %0, {%1, %1};" : "=l"(wd1) : "f"(w[u + 1]));
#pragma unroll
            for (int i = 0; i < 4; i++) {
                ulonglong2 xv = *(const ulonglong2*)&xs2[i * 256 + k0 + u];
                asm("fma.rn.f32x2 %0, %1, %2, %0;" : "+l"(acc[i]) : "l"(xv.x), "l"(wd0));
                asm("fma.rn.f32x2 %0, %1, %2, %0;" : "+l"(acc[i]) : "l"(xv.y), "l"(wd1));
            }
        }
    }

    float bb = bg[tid], s = 0.f;
#pragma unroll
    for (int i = 0; i < 4; i++) {
        float lo, hi;
        asm("mov.b64 {%0, %1}, %2;" : "=f"(lo), "=f"(hi) : "l"(acc[i]));
        float z0 = lo + bb, z1 = hi + bb;
        s += (z0 > 0.f) ? z0 : 0.2f * z0;
        s += (z1 > 0.f) ? z1 : 0.2f * z1;
    }
    atomicAdd(&gv[tid], s);
}

__global__ void cosine_kernel() {
    __shared__ float red[24];
    int tid = threadIdx.x;
    float v1 = g_v1[tid] * (1.0f / NN);
    float v2 = g_v2[tid] * (1.0f / NN);
    float d = v1 * v2, a = v1 * v1, b = v2 * v2;
    d = warpRedSum(d); a = warpRedSum(a); b = warpRedSum(b);
    if ((tid & 31) == 0) {
        red[tid >> 5] = d; red[8 + (tid >> 5)] = a; red[16 + (tid >> 5)] = b;
    }
    __syncthreads();
    if (tid == 0) {
        float D = 0.f, A = 0.f, B = 0.f;
#pragma unroll
        for (int i = 0; i < 8; i++) { D += red[i]; A += red[8 + i]; B += red[16 + i]; }
        g_y = 1.0f - D / (sqrtf(A) * sqrtf(B) + 1e-8f);
    }
}

// fused tail: a1[i,j] = max(-cost[i,j] - tau_col[j], 0)  AND  cost_out = y
__global__ void tail_kernel(const float* __restrict__ cost,
                            float* __restrict__ a1, float* __restrict__ cost_out) {
    size_t idx = ((size_t)blockIdx.x * blockDim.x + threadIdx.x) * 4;
    int j = (int)(idx & (NN - 1));
    float4 c = *(const float4*)(cost + idx);
    const float4 tc = *(const float4*)(g_tau_col + j);
    float4 o;
    o.x = fmaxf(-c.x - tc.x, 0.f);
    o.y = fmaxf(-c.y - tc.y, 0.f);
    o.z = fmaxf(-c.z - tc.z, 0.f);
    o.w = fmaxf(-c.w - tc.w, 0.f);
    __stcs((float4*)(a1 + idx), o);
    float y = g_y;
    __stcs((float4*)(cost_out + idx), make_float4(y, y, y, y));
}

// ---------------- launch ----------------
extern "C" void kernel_launch(void* const* d_in, const int* in_sizes, int n_in,
                              void* d_out, int out_size) {
    const float* row_vecs    = (const float*)d_in[0];
    const float* column_vecs = (const float*)d_in[1];
    const float* cost        = (const float*)d_in[2];
    const float* W_G         = (const float*)d_in[3];
    const float* b_G         = (const float*)d_in[4];

    float* out      = (float*)d_out;
    float* cost_out = out;
    float* a0       = out + (size_t)NN * NN;
    float* a1       = out + 2 * (size_t)NN * NN;

    (void)in_sizes; (void)n_in; (void)out_size;

    zero_kernel<<<16, 256>>>();
    colmax_kernel<<<dim3(NN / 256, NN / 64), 256>>>(cost);
    thr_kernel<<<16, 256>>>();
    spmax_row_kernel<<<NN, 256>>>(cost, a0, column_vecs);   // a0, beta, col candidates
    col_alpha_kernel<<<NN, 256>>>(cost, row_vecs);          // tau_col, alpha
    g_mean_kernel<<<dim3(NN / 8, 2), 256>>>(W_G, b_G);      // v1 & v2 (8 rows/block)
    cosine_kernel<<<1, 256>>>();
    tail_kernel<<<(NN * (size_t)NN) / (4 * 256), 256>>>(cost, a1, cost_out);
}

// round 13
// speedup vs baseline: 1.7529x; 1.0655x over previous
#include <cuda_runtime.h>
#include <math.h>

#define NN 4096
#define DD 256
#define CAPS 1024     // row support capacity (smem)
#define CCAP 1024     // per-column candidate capacity (global)

// ---------------- device scratch ----------------
__device__ unsigned g_colmax_enc[NN];
__device__ float    g_colthr[NN];
__device__ int      g_colcnt[NN];
__device__ float    g_colval[(size_t)NN * CCAP];
__device__ unsigned short g_colrow[(size_t)NN * CCAP];
__device__ float g_tau_col[NN];
__device__ float g_beta[(size_t)NN * DD];
__device__ float g_alpha[(size_t)NN * DD];
__device__ float g_v1[DD];
__device__ float g_v2[DD];
__device__ float g_y;

__device__ __forceinline__ unsigned encf(float f) {
    unsigned i = __float_as_uint(f);
    return (i & 0x80000000u) ? ~i : (i | 0x80000000u);
}
__device__ __forceinline__ float decf(unsigned u) {
    return (u & 0x80000000u) ? __uint_as_float(u & 0x7fffffffu) : __uint_as_float(~u);
}

__device__ __forceinline__ float warpRedSum(float v) {
#pragma unroll
    for (int o = 16; o > 0; o >>= 1) v += __shfl_xor_sync(0xffffffffu, v, o);
    return v;
}
__device__ __forceinline__ float warpRedMax(float v) {
#pragma unroll
    for (int o = 16; o > 0; o >>= 1) v = fmaxf(v, __shfl_xor_sync(0xffffffffu, v, o));
    return v;
}

__device__ __forceinline__ int blockScanExcl(int cnt, int& total, int tid) {
    __shared__ int warp_tot[8];
    const unsigned mask = 0xffffffffu;
    int lane = tid & 31, w = tid >> 5;
    int incl = cnt;
#pragma unroll
    for (int o = 1; o < 32; o <<= 1) {
        int n = __shfl_up_sync(mask, incl, o);
        if (lane >= o) incl += n;
    }
    if (lane == 31) warp_tot[w] = incl;
    __syncthreads();
    if (w == 0) {
        int t = (lane < 8) ? warp_tot[lane] : 0;
#pragma unroll
        for (int o = 1; o < 8; o <<= 1) {
            int n = __shfl_up_sync(mask, t, o);
            if (lane >= o) t += n;
        }
        if (lane < 8) warp_tot[lane] = t;
    }
    __syncthreads();
    int warp_off = (w == 0) ? 0 : warp_tot[w - 1];
    total = warp_tot[7];
    __syncthreads();
    return warp_off + incl - cnt;
}

// ---------------- kernels ----------------
__global__ void zero_kernel() {
    int t = blockIdx.x * 256 + threadIdx.x;
    g_colcnt[t] = 0;
    g_colmax_enc[t] = 0u;
    if (t < DD) { g_v1[t] = 0.f; g_v2[t] = 0.f; }
}

__global__ __launch_bounds__(256) void colmax_kernel(const float* __restrict__ cost) {
    int c = blockIdx.x * 256 + threadIdx.x;
    size_t r0 = (size_t)blockIdx.y * 64;
    float m = -3.0e38f;
#pragma unroll 8
    for (int r = 0; r < 64; r++)
        m = fmaxf(m, -cost[(r0 + r) * NN + c]);
    atomicMax(&g_colmax_enc[c], encf(m));
}

__global__ void thr_kernel() {
    int t = blockIdx.x * 256 + threadIdx.x;
    g_colthr[t] = decf(g_colmax_enc[t]) - 1.0f;
}

// row sparsemax + a0 + beta mix + column-candidate harvest (round-10 proven form)
__global__ __launch_bounds__(256) void spmax_row_kernel(const float* __restrict__ cost,
                                                        float* __restrict__ a0,
                                                        const float* __restrict__ colvecs) {
    __shared__ float red[8 + 64];
    __shared__ float s_p[CAPS];
    __shared__ unsigned short s_j[CAPS];
    int tid = threadIdx.x;
    int row = blockIdx.x;
    const float* xrow = cost + (size_t)row * NN;

    float x[16];
    float vmax = -3.0e38f;
#pragma unroll
    for (int k = 0; k < 4; k++) {
        float4 v = *(const float4*)(xrow + tid * 4 + k * 1024);
        x[k * 4 + 0] = -v.x; x[k * 4 + 1] = -v.y;
        x[k * 4 + 2] = -v.z; x[k * 4 + 3] = -v.w;
        vmax = fmaxf(vmax, fmaxf(fmaxf(-v.x, -v.y), fmaxf(-v.z, -v.w)));
    }

    float m = warpRedMax(vmax);
    if ((tid & 31) == 0) red[tid >> 5] = m;
    __syncthreads();
    float bm = red[0];
#pragma unroll
    for (int i = 1; i < 8; i++) bm = fmaxf(bm, red[i]);

    float tau = bm - 1.0f;
    int kprev = -1;
    for (int it = 0; it < 64; ++it) {
        float ls = 0.f, lc = 0.f;
#pragma unroll
        for (int s = 0; s < 16; s++) {
            float v = x[s];
            if (v > tau) { ls += v; lc += 1.0f; }
        }
        ls = warpRedSum(ls);
        lc = warpRedSum(lc);
        int p = it & 1;
        float* buf = red + 8 + p * 32;
        if ((tid & 31) == 0) { buf[tid >> 5] = ls; buf[8 + (tid >> 5)] = lc; }
        __syncthreads();
        float S = 0.f, K = 0.f;
#pragma unroll
        for (int i = 0; i < 8; i++) { S += buf[i]; K += buf[8 + i]; }
        int k = (int)K;
        if (k == kprev) break;
        tau = (S - 1.0f) / K;
        kprev = k;
    }

#pragma unroll
    for (int k = 0; k < 4; k++) {
        int j = tid * 4 + k * 1024;
        float4 o;
        o.x = fmaxf(x[k * 4 + 0] - tau, 0.f);
        o.y = fmaxf(x[k * 4 + 1] - tau, 0.f);
        o.z = fmaxf(x[k * 4 + 2] - tau, 0.f);
        o.w = fmaxf(x[k * 4 + 3] - tau, 0.f);
        __stcs((float4*)(a0 + (size_t)row * NN + j), o);

        float4 th = *(const float4*)(g_colthr + j);
#pragma unroll
        for (int c = 0; c < 4; c++) {
            float xv = x[k * 4 + c];
            float tt = (c == 0) ? th.x : (c == 1) ? th.y : (c == 2) ? th.z : th.w;
            if (xv > tt) {
                int jj = j + c;
                int pos = atomicAdd(&g_colcnt[jj], 1);
                if (pos < CCAP) {
                    g_colval[(size_t)jj * CCAP + pos] = xv;
                    g_colrow[(size_t)jj * CCAP + pos] = (unsigned short)row;
                }
            }
        }
    }

    int cnt = 0;
#pragma unroll
    for (int s = 0; s < 16; s++)
        if (x[s] > tau) cnt++;
    int nnz;
    int base = blockScanExcl(cnt, nnz, tid);
    if (nnz <= CAPS) {
        int pos = base;
#pragma unroll
        for (int s = 0; s < 16; s++) {
            if (x[s] > tau) {
                s_p[pos] = x[s] - tau;
                s_j[pos] = (unsigned short)(tid * 4 + (s >> 2) * 1024 + (s & 3));
                pos++;
            }
        }
    }
    __syncthreads();

    float acc = 0.f;
    if (nnz <= CAPS) {
#pragma unroll 4
        for (int n = 0; n < nnz; n++)
            acc = fmaf(s_p[n], colvecs[(size_t)s_j[n] * DD + tid], acc);
    } else {
        for (int j = 0; j < NN; j++) {
            float p = -xrow[j] - tau;
            if (p > 0.f) acc = fmaf(p, colvecs[(size_t)j * DD + tid], acc);
        }
    }
    g_beta[(size_t)row * DD + tid] = acc;
}

// per-column: exact Michelot on candidate list -> tau_col + alpha[j,:]
__global__ __launch_bounds__(256) void col_alpha_kernel(const float* __restrict__ cost,
                                                        const float* __restrict__ rowvecs) {
    __shared__ float sv[CCAP];
    __shared__ unsigned short si[CCAP];
    __shared__ float s_tau;
    int j = blockIdx.x;
    int tid = threadIdx.x, lane = tid & 31;
    int cnt = g_colcnt[j];

    if (cnt <= CCAP) {
        for (int n = tid; n < cnt; n += 256) {
            sv[n] = g_colval[(size_t)j * CCAP + n];
            si[n] = g_colrow[(size_t)j * CCAP + n];
        }
        __syncthreads();
        if (tid < 32) {
            float ls = 0.f;
            for (int n = lane; n < cnt; n += 32) ls += sv[n];
            ls = warpRedSum(ls);
            float t = (ls - 1.0f) / (float)cnt;
            int kprev = cnt;
            for (int it = 0; it < 48; ++it) {
                float s = 0.f, c = 0.f;
                for (int n = lane; n < cnt; n += 32) {
                    float v = sv[n];
                    if (v > t) { s += v; c += 1.0f; }
                }
                s = warpRedSum(s);
                c = warpRedSum(c);
                int k = (int)c;
                if (k == kprev) break;
                t = (s - 1.0f) / c;
                kprev = k;
            }
            if (lane == 0) s_tau = t;
        }
        __syncthreads();
        float tau = s_tau;
        if (tid == 0) g_tau_col[j] = tau;

        for (int n = tid; n < cnt; n += 256)
            sv[n] = fmaxf(sv[n] - tau, 0.f);
        __syncthreads();

        float acc0 = 0.f, acc1 = 0.f;
        int n = 0;
        for (; n + 4 <= cnt; n += 4) {
            float p0 = sv[n + 0], p1 = sv[n + 1], p2 = sv[n + 2], p3 = sv[n + 3];
            float m0 = rowvecs[(size_t)si[n + 0] * DD + tid];
            float m1 = rowvecs[(size_t)si[n + 1] * DD + tid];
            float m2 = rowvecs[(size_t)si[n + 2] * DD + tid];
            float m3 = rowvecs[(size_t)si[n + 3] * DD + tid];
            acc0 = fmaf(p0, m0, acc0);
            acc1 = fmaf(p1, m1, acc1);
            acc0 = fmaf(p2, m2, acc0);
            acc1 = fmaf(p3, m3, acc1);
        }
        for (; n < cnt; n++)
            acc0 = fmaf(sv[n], rowvecs[(size_t)si[n] * DD + tid], acc0);
        g_alpha[(size_t)j * DD + tid] = acc0 + acc1;
    } else {
        if (tid < 32) {
            float t = g_colthr[j];
            int kprev = -1;
            for (int it = 0; it < 64; ++it) {
                float s = 0.f, c = 0.f;
                for (int r = lane; r < NN; r += 32) {
                    float v = -cost[(size_t)r * NN + j];
                    if (v > t) { s += v; c += 1.0f; }
                }
                s = warpRedSum(s);
                c = warpRedSum(c);
                int k = (int)c;
                if (k == kprev) break;
                t = (s - 1.0f) / c;
                kprev = k;
            }
            if (lane == 0) s_tau = t;
        }
        __syncthreads();
        float tau = s_tau;
        if (tid == 0) g_tau_col[j] = tau;
        float acc = 0.f;
        for (int r = 0; r < NN; r++) {
            float p = -cost[(size_t)r * NN + j] - tau;
            if (p > 0.f) acc = fmaf(p, rowvecs[(size_t)r * DD + tid], acc);
        }
        g_alpha[(size_t)j * DD + tid] = acc;
    }
}

// ---------------- fused mid kernel: g_mean (blocks 0..511) + a1 stream (rest) ----
// g_mean: leaky_relu(X @ W + b) partial means, packed f32x2, 16 rows/block.
// a1 blocks: a1[i,j] = max(-cost[i,j] - tau_col[j], 0), float4 streaming.
#define GM_BLOCKS 512                       // 256 per matrix
#define A1_BLOCKS (NN * NN / (4 * 256))     // 16384

__global__ __launch_bounds__(256) void fused_mid_kernel(const float* __restrict__ Wg,
                                                        const float* __restrict__ bg,
                                                        const float* __restrict__ cost,
                                                        float* __restrict__ a1) {
    int b = blockIdx.x;
    int tid = threadIdx.x;

    if (b >= GM_BLOCKS) {
        // streaming a1 block
        size_t idx = ((size_t)(b - GM_BLOCKS) * 256 + tid) * 4;
        int j = (int)(idx & (NN - 1));
        float4 c = *(const float4*)(cost + idx);
        const float4 tc = *(const float4*)(g_tau_col + j);
        float4 o;
        o.x = fmaxf(-c.x - tc.x, 0.f);
        o.y = fmaxf(-c.y - tc.y, 0.f);
        o.z = fmaxf(-c.z - tc.z, 0.f);
        o.w = fmaxf(-c.w - tc.w, 0.f);
        __stcs((float4*)(a1 + idx), o);
        return;
    }

    // g_mean block (round-10 proven form, 16 rows/block)
    int which = (b >= 256) ? 1 : 0;
    int rb = which ? (b - 256) : b;
    const float* Xall = which ? g_alpha : g_beta;
    float* gv = which ? g_v2 : g_v1;
    __shared__ unsigned long long xs2[8 * 256];
    size_t r0 = (size_t)rb * 16;

#pragma unroll
    for (int i = 0; i < 8; i++) {
        float a = Xall[(r0 + 2 * i) * 256 + tid];
        float bv = Xall[(r0 + 2 * i + 1) * 256 + tid];
        unsigned long long p;
        asm("mov.b64 %0, {%1, %2};" : "=l"(p) : "f"(a), "f"(bv));
        xs2[i * 256 + tid] = p;
    }
    __syncthreads();

    unsigned long long acc[8];
#pragma unroll
    for (int i = 0; i < 8; i++) acc[i] = 0ull;

    for (int k0 = 0; k0 < 256; k0 += 8) {
        float w[8];
#pragma unroll
        for (int u = 0; u < 8; u++) w[u] = Wg[(size_t)(k0 + u) * 256 + tid];
#pragma unroll
        for (int u = 0; u < 8; u += 2) {
            unsigned long long wd0, wd1;
            asm("mov.b64 %0, {%1, %1};" : "=l"(wd0) : "f"(w[u]));
            asm("mov.b64 %0, {%1, %1};" : "=l"(wd1) : "f"(w[u + 1]));
#pragma unroll
            for (int i = 0; i < 8; i++) {
                ulonglong2 xv = *(const ulonglong2*)&xs2[i * 256 + k0 + u];
                asm("fma.rn.f32x2 %0, %1, %2, %0;" : "+l"(acc[i]) : "l"(xv.x), "l"(wd0));
                asm("fma.rn.f32x2 %0, %1, %2, %0;" : "+l"(acc[i]) : "l"(xv.y), "l"(wd1));
            }
        }
    }

    float bb = bg[tid], s = 0.f;
#pragma unroll
    for (int i = 0; i < 8; i++) {
        float lo, hi;
        asm("mov.b64 {%0, %1}, %2;" : "=f"(lo), "=f"(hi) : "l"(acc[i]));
        float z0 = lo + bb, z1 = hi + bb;
        s += (z0 > 0.f) ? z0 : 0.2f * z0;
        s += (z1 > 0.f) ? z1 : 0.2f * z1;
    }
    atomicAdd(&gv[tid], s);
}

__global__ void cosine_kernel() {
    __shared__ float red[24];
    int tid = threadIdx.x;
    float v1 = g_v1[tid] * (1.0f / NN);
    float v2 = g_v2[tid] * (1.0f / NN);
    float d = v1 * v2, a = v1 * v1, b = v2 * v2;
    d = warpRedSum(d); a = warpRedSum(a); b = warpRedSum(b);
    if ((tid & 31) == 0) {
        red[tid >> 5] = d; red[8 + (tid >> 5)] = a; red[16 + (tid >> 5)] = b;
    }
    __syncthreads();
    if (tid == 0) {
        float D = 0.f, A = 0.f, B = 0.f;
#pragma unroll
        for (int i = 0; i < 8; i++) { D += red[i]; A += red[8 + i]; B += red[16 + i]; }
        g_y = 1.0f - D / (sqrtf(A) * sqrtf(B) + 1e-8f);
    }
}

__global__ void fill_kernel(float* __restrict__ out) {
    float y = g_y;
    size_t idx = ((size_t)blockIdx.x * blockDim.x + threadIdx.x) * 4;
    __stcs((float4*)(out + idx), make_float4(y, y, y, y));
}

// ---------------- launch ----------------
extern "C" void kernel_launch(void* const* d_in, const int* in_sizes, int n_in,
                              void* d_out, int out_size) {
    const float* row_vecs    = (const float*)d_in[0];
    const float* column_vecs = (const float*)d_in[1];
    const float* cost        = (const float*)d_in[2];
    const float* W_G         = (const float*)d_in[3];
    const float* b_G         = (const float*)d_in[4];

    float* out      = (float*)d_out;
    float* cost_out = out;
    float* a0       = out + (size_t)NN * NN;
    float* a1       = out + 2 * (size_t)NN * NN;

    (void)in_sizes; (void)n_in; (void)out_size;

    zero_kernel<<<16, 256>>>();
    colmax_kernel<<<dim3(NN / 256, NN / 64), 256>>>(cost);
    thr_kernel<<<16, 256>>>();
    spmax_row_kernel<<<NN, 256>>>(cost, a0, column_vecs);     // a0, beta, col candidates
    col_alpha_kernel<<<NN, 256>>>(cost, row_vecs);            // tau_col, alpha
    fused_mid_kernel<<<GM_BLOCKS + A1_BLOCKS, 256>>>(W_G, b_G, cost, a1);  // v1, v2, a1
    cosine_kernel<<<1, 256>>>();
    fill_kernel<<<(NN * (size_t)NN) / (4 * 256), 256>>>(cost_out);
}